// round 12
// baseline (speedup 1.0000x reference)
#include <cuda_runtime.h>
#include <cuda_bf16.h>
#include <cstdint>

#define NN 4096
#define DD 512
#define NCLS 64
#define CMAX 160
#define NTRI 528            // 32*33/2 upper-tri 128x128 tiles

// ---------------- device globals (scratch; no runtime alloc) ----------------
__device__ int   g_tgt[NN];
__device__ int   g_rank[NN];
__device__ int   g_members[NCLS * CMAX];
__device__ int   g_count[NCLS];
__device__ float g_sq[NN];
__device__ float g_negsum[NN];
__device__ float g_loss;
__device__ float g_pd[NCLS * CMAX * CMAX];   // dist for same-class pairs (ri<rj)
__device__ uint4 g_hi4[NN * DD / 8];         // bf16 hi split, row-major (64 uint4/row)
__device__ uint4 g_lo4[NN * DD / 8];         // bf16 lo split

// ---------------- PTX helpers ----------------
__device__ __forceinline__ uint32_t s2u(const void* p) {
    uint32_t a;
    asm("{ .reg .u64 t; cvta.to.shared.u64 t, %1; cvt.u32.u64 %0, t; }"
        : "=r"(a) : "l"(p));
    return a;
}
__device__ __forceinline__ void cp16(uint32_t saddr, const void* g) {
    asm volatile("cp.async.cg.shared.global [%0], [%1], 16;" :: "r"(saddr), "l"(g));
}
#define CP_COMMIT() asm volatile("cp.async.commit_group;" ::: "memory")
#define CP_WAIT1()  asm volatile("cp.async.wait_group 1;" ::: "memory")
#define CP_WAIT0()  asm volatile("cp.async.wait_group 0;" ::: "memory")

__device__ __forceinline__ void ldm_x4(uint32_t& r0, uint32_t& r1, uint32_t& r2,
                                       uint32_t& r3, uint32_t a) {
    asm volatile("ldmatrix.sync.aligned.m8n8.x4.shared.b16 {%0,%1,%2,%3}, [%4];"
                 : "=r"(r0), "=r"(r1), "=r"(r2), "=r"(r3) : "r"(a));
}
__device__ __forceinline__ void mma16816(float* d, const uint32_t* a, const uint32_t* b) {
    asm volatile(
        "mma.sync.aligned.m16n8k16.row.col.f32.bf16.bf16.f32 "
        "{%0,%1,%2,%3}, {%4,%5,%6,%7}, {%8,%9}, {%0,%1,%2,%3};"
        : "+f"(d[0]), "+f"(d[1]), "+f"(d[2]), "+f"(d[3])
        : "r"(a[0]), "r"(a[1]), "r"(a[2]), "r"(a[3]), "r"(b[0]), "r"(b[1]));
}
#define SW64(bo) ((bo) ^ (((bo) >> 3) & 0x30))

// ---------------- fast math (no MUFU on hot path) ----------------
__device__ __forceinline__ float fast_dist(float d2) {
    float y = __int_as_float(0x5f3759dfu - (__float_as_uint(d2) >> 1));
    y = y * fmaf(-0.5f * d2, y * y, 1.5f);
    y = y * fmaf(-0.5f * d2, y * y, 1.5f);
    y = y * fmaf(-0.5f * d2, y * y, 1.5f);
    return d2 > 1e-18f ? d2 * y : 0.0f;
}
__device__ __forceinline__ float exp1m(float dist) {  // exp(1 - dist)
    float t = (1.0f - dist) * 1.4426950408889634f;
    t = fmaxf(t, -125.0f);
    int n = __float2int_rn(t);
    float f = t - (float)n;
    float p = 1.3333558146e-3f;
    p = fmaf(p, f, 9.6181291076e-3f);
    p = fmaf(p, f, 5.5504108664e-2f);
    p = fmaf(p, f, 2.4022650696e-1f);
    p = fmaf(p, f, 6.9314718056e-1f);
    p = fmaf(p, f, 1.0f);
    return __int_as_float((uint32_t)(n + 127) << 23) * p;
}

// ---------------------------------------------------------------------------
// K-1: dtype-normalize targets (int32 or int64). One block, trivial.
// ---------------------------------------------------------------------------
__global__ __launch_bounds__(1024) void k_cvt(const int* __restrict__ t) {
    __shared__ int any_odd;
    int tid = threadIdx.x;
    if (tid == 0) any_odd = 0;
    __syncthreads();
    int local = 0;
    for (int i = tid; i < NN / 2; i += 1024) local |= t[2 * i + 1];
    if (local) atomicOr(&any_odd, 1);
    __syncthreads();
    bool is64 = (any_odd == 0);
    for (int i = tid; i < NN; i += 1024) g_tgt[i] = is64 ? t[2 * i] : t[i];
}

// ---------------------------------------------------------------------------
// K-0.5: per-class rank/members via block-wide ballot prefix scan.
// ---------------------------------------------------------------------------
__global__ __launch_bounds__(256) void k_rank() {
    const int c = blockIdx.x, tid = threadIdx.x;
    const int wid = tid >> 5, lane = tid & 31;
    __shared__ int wtot[8], wpre[8];
    __shared__ int base;
    if (tid == 0) base = 0;
    __syncthreads();
    for (int r0 = 0; r0 < NN; r0 += 256) {
        int i = r0 + tid;
        bool f = (g_tgt[i] == c);
        unsigned m = __ballot_sync(0xffffffffu, f);
        int myoff = __popc(m & ((1u << lane) - 1u));
        if (lane == 0) wtot[wid] = __popc(m);
        __syncthreads();
        if (tid < 8) {
            int s = 0;
            for (int w = 0; w < tid; w++) s += wtot[w];
            wpre[tid] = s;
        }
        __syncthreads();
        if (f) {
            int rk = base + wpre[wid] + myoff;
            g_rank[i] = rk;
            if (rk < CMAX) g_members[c * CMAX + rk] = i;
        }
        __syncthreads();
        if (tid == 0) {
            int s = 0;
            for (int w = 0; w < 8; w++) s += wtot[w];
            base += s;
        }
        __syncthreads();
    }
    if (tid == 0) g_count[c] = base;
}

// ---------------------------------------------------------------------------
// K0: row norms + bf16 hi/lo split + zero accumulators
// ---------------------------------------------------------------------------
__global__ __launch_bounds__(256) void k_sq_split(const float* __restrict__ X) {
    int warp = threadIdx.x >> 5, lane = threadIdx.x & 31;
    int row = blockIdx.x * 8 + warp;
    const float4* xr = (const float4*)(X + (size_t)row * DD);
    uint2* hi2 = (uint2*)g_hi4;
    uint2* lo2 = (uint2*)g_lo4;
    float s = 0.f;
#pragma unroll
    for (int q = 0; q < 4; q++) {
        int i4 = lane + q * 32;
        float4 v = xr[i4];
        s += v.x * v.x + v.y * v.y + v.z * v.z + v.w * v.w;
        union { __nv_bfloat16 b[4]; uint2 u; } H, L;
        H.b[0] = __float2bfloat16(v.x); H.b[1] = __float2bfloat16(v.y);
        H.b[2] = __float2bfloat16(v.z); H.b[3] = __float2bfloat16(v.w);
        L.b[0] = __float2bfloat16(v.x - __bfloat162float(H.b[0]));
        L.b[1] = __float2bfloat16(v.y - __bfloat162float(H.b[1]));
        L.b[2] = __float2bfloat16(v.z - __bfloat162float(H.b[2]));
        L.b[3] = __float2bfloat16(v.w - __bfloat162float(H.b[3]));
        hi2[(size_t)row * 128 + i4] = H.u;
        lo2[(size_t)row * 128 + i4] = L.u;
    }
#pragma unroll
    for (int o = 16; o; o >>= 1) s += __shfl_xor_sync(0xffffffffu, s, o);
    if (lane == 0) { g_sq[row] = s; g_negsum[row] = 0.f; }
    if (blockIdx.x == 0 && threadIdx.x == 0) g_loss = 0.f;
}

// ---------------------------------------------------------------------------
// K1: split-bf16 symmetric GEMM via ldmatrix + mma.sync, fused epilogue.
// BK=32, 3-stage cp.async pipeline (96 KB) -> 2 CTAs/SM.
// ---------------------------------------------------------------------------
#define BUFSZ 8192                // one operand chunk: 128 rows x 64B
#define PHSZ  (4 * BUFSZ)         // Ahi,Alo,Bhi,Blo = 32 KB
#define NSTAGE 3
#define NCHUNK 16                 // K=512 / 32
#define SMEM_DYN (NSTAGE * PHSZ)  // 96 KB

__device__ __forceinline__ void load_chunk(uint32_t dynb, int stage, int m0, int n0,
                                           int kq4, int tid) {
#pragma unroll
    for (int op = 0; op < 4; op++) {
        const uint4* src = (op & 1) ? g_lo4 : g_hi4;
        int rb = (op < 2) ? m0 : n0;
        uint32_t dst = dynb + stage * PHSZ + op * BUFSZ;
#pragma unroll
        for (int u = 0; u < 2; u++) {
            int f = tid + u * 256;                 // 0..511
            int r = f >> 2, c4 = f & 3;
            uint32_t bo = (uint32_t)(r * 64 + c4 * 16);
            cp16(dst + SW64(bo), &src[(size_t)(rb + r) * 64 + kq4 + c4]);
        }
    }
}

__global__ __launch_bounds__(256, 2) void k_gemm_mma() {
    extern __shared__ __align__(1024) char dyn[];
    __shared__ int   tR[128], tC[128], rkR[128], rkC[128];
    __shared__ float sqR[128], sqC[128], rowsum[128], colsum[128];

    const int tid = threadIdx.x;
    const int lane = tid & 31;
    const int wid = tid >> 5;
    const int wm = wid & 3, wn = wid >> 2;
    const uint32_t dynb = s2u(dyn);

    // upper-tri tile decode: blk = bj*(bj+1)/2 + bi, bi<=bj
    int k = blockIdx.x;
    int bj = (int)((sqrtf(8.f * (float)k + 1.f) - 1.f) * 0.5f);
    while ((bj + 1) * (bj + 2) / 2 <= k) bj++;
    while (bj * (bj + 1) / 2 > k) bj--;
    int bi = k - bj * (bj + 1) / 2;
    const int m0 = bi * 128, n0 = bj * 128;
    const bool offdiag = (bi != bj);

    for (int t = tid; t < 128; t += 256) {
        tR[t] = g_tgt[m0 + t];   tC[t] = g_tgt[n0 + t];
        sqR[t] = g_sq[m0 + t];   sqC[t] = g_sq[n0 + t];
        rkR[t] = g_rank[m0 + t]; rkC[t] = g_rank[n0 + t];
        rowsum[t] = 0.f;         colsum[t] = 0.f;
    }

    float acc[2][8][4];
#pragma unroll
    for (int mi = 0; mi < 2; mi++)
#pragma unroll
        for (int nf = 0; nf < 8; nf++)
#pragma unroll
            for (int e = 0; e < 4; e++) acc[mi][nf][e] = 0.f;

    load_chunk(dynb, 0, m0, n0, 0, tid); CP_COMMIT();
    load_chunk(dynb, 1, m0, n0, 4, tid); CP_COMMIT();

    const int mat = lane >> 3, rr = lane & 7;

    for (int ci = 0; ci < NCHUNK; ci++) {
        const int cur = ci % NSTAGE;
        CP_WAIT1();
        __syncthreads();            // chunk ci ready everywhere; ci-1 consumed

        const uint32_t Ah = dynb + cur * PHSZ;
        const uint32_t Al = Ah + BUFSZ;
        const uint32_t Bh = Ah + 2 * BUFSZ;
        const uint32_t Bl = Ah + 3 * BUFSZ;

#pragma unroll
        for (int ks = 0; ks < 2; ks++) {
            uint32_t ahi[2][4], alo[2][4];
#pragma unroll
            for (int mi = 0; mi < 2; mi++) {
                int row = wm * 32 + mi * 16 + (mat & 1) * 8 + rr;
                uint32_t bo = (uint32_t)(row * 64 + ks * 32 + (mat >> 1) * 16);
                uint32_t sw = SW64(bo);
                ldm_x4(ahi[mi][0], ahi[mi][1], ahi[mi][2], ahi[mi][3], Ah + sw);
                ldm_x4(alo[mi][0], alo[mi][1], alo[mi][2], alo[mi][3], Al + sw);
            }
#pragma unroll
            for (int half = 0; half < 2; half++) {
                uint32_t bhi[4][2], blo[4][2];
#pragma unroll
                for (int qh = 0; qh < 2; qh++) {
                    int q = half * 2 + qh;
                    int row = wn * 64 + q * 16 + (mat >> 1) * 8 + rr;
                    uint32_t bo = (uint32_t)(row * 64 + ks * 32 + (mat & 1) * 16);
                    uint32_t sw = SW64(bo);
                    uint32_t r0, r1, r2, r3;
                    ldm_x4(r0, r1, r2, r3, Bh + sw);
                    bhi[2 * qh][0] = r0;     bhi[2 * qh][1] = r1;
                    bhi[2 * qh + 1][0] = r2; bhi[2 * qh + 1][1] = r3;
                    ldm_x4(r0, r1, r2, r3, Bl + sw);
                    blo[2 * qh][0] = r0;     blo[2 * qh][1] = r1;
                    blo[2 * qh + 1][0] = r2; blo[2 * qh + 1][1] = r3;
                }
#pragma unroll
                for (int mi = 0; mi < 2; mi++)
#pragma unroll
                    for (int l = 0; l < 4; l++) {
                        mma16816(acc[mi][half * 4 + l], ahi[mi], bhi[l]);
                        mma16816(acc[mi][half * 4 + l], ahi[mi], blo[l]);
                        mma16816(acc[mi][half * 4 + l], alo[mi], bhi[l]);
                    }
            }
        }
        if (ci + 2 < NCHUNK) {
            load_chunk(dynb, (ci + 2) % NSTAGE, m0, n0, (ci + 2) * 4, tid);
            CP_COMMIT();
        } else {
            CP_COMMIT();            // keep group count in step for CP_WAIT1
        }
    }

    // ---- epilogue: dist, masked exp, row/col negsums, pos-pair dist store ----
    const int tq = lane >> 2, tr = lane & 3;
    float csum[8][2];
#pragma unroll
    for (int nf = 0; nf < 8; nf++) { csum[nf][0] = 0.f; csum[nf][1] = 0.f; }

#pragma unroll
    for (int mi = 0; mi < 2; mi++) {
#pragma unroll
        for (int h = 0; h < 2; h++) {
            int row = wm * 32 + mi * 16 + tq + h * 8;
            int ti = tR[row]; float si = sqR[row]; int ri = rkR[row];
            int gi = m0 + row;
            float rsum = 0.f;
#pragma unroll
            for (int nf = 0; nf < 8; nf++) {
#pragma unroll
                for (int p = 0; p < 2; p++) {
                    int col = wn * 64 + nf * 8 + tr * 2 + p;
                    float dot = acc[mi][nf][h * 2 + p];
                    float d2 = fmaxf(si + sqC[col] - 2.f * dot, 0.f);
                    float dist = fast_dist(d2);
                    bool same = (ti == tC[col]);
                    float ev = same ? 0.f : exp1m(dist);
                    rsum += ev;
                    csum[nf][p] += ev;
                    if (same) {
                        int gj = n0 + col;
                        if (gi < gj) {
                            int rj = rkC[col];
                            if (ri < CMAX && rj < CMAX)
                                g_pd[(ti * CMAX + ri) * CMAX + rj] = dist;
                        }
                    }
                }
            }
            rsum += __shfl_xor_sync(0xffffffffu, rsum, 1);
            rsum += __shfl_xor_sync(0xffffffffu, rsum, 2);
            if (tr == 0) atomicAdd(&rowsum[row], rsum);
        }
    }
    if (offdiag) {
#pragma unroll
        for (int nf = 0; nf < 8; nf++)
#pragma unroll
            for (int p = 0; p < 2; p++) {
                float v = csum[nf][p];
                v += __shfl_xor_sync(0xffffffffu, v, 4);
                v += __shfl_xor_sync(0xffffffffu, v, 8);
                v += __shfl_xor_sync(0xffffffffu, v, 16);
                if (lane < 4) atomicAdd(&colsum[wn * 64 + nf * 8 + lane * 2 + p], v);
            }
    }
    __syncthreads();
    for (int t = tid; t < 128; t += 256) {
        atomicAdd(&g_negsum[m0 + t], rowsum[t]);
        if (offdiag) atomicAdd(&g_negsum[n0 + t], colsum[t]);
    }
}

// ---------------------------------------------------------------------------
// K2: positive-pair loss. Thread-per-pair flattened triangular decode.
// ---------------------------------------------------------------------------
__global__ __launch_bounds__(256) void k_pairs2() {
    __shared__ float ns[CMAX];
    __shared__ float wsum[8];
    const int c = blockIdx.x, tid = threadIdx.x;
    int cnt = g_count[c];
    if (cnt > CMAX) cnt = CMAX;
    for (int t = tid; t < cnt; t += 256)
        ns[t] = g_negsum[g_members[c * CMAX + t]];
    __syncthreads();

    const int P = cnt * (cnt - 1) / 2;
    float acc = 0.f;
    for (int p = tid; p < P; p += 256) {
        float fn = (float)cnt;
        float disc = (2.f * fn - 1.f) * (2.f * fn - 1.f) - 8.f * (float)p;
        int a = (int)((2.f * fn - 1.f - sqrtf(fmaxf(disc, 0.f))) * 0.5f);
        if (a < 0) a = 0;
        while (a > 0 && a * cnt - a * (a + 1) / 2 > p) a--;
        while ((a + 1) * cnt - (a + 1) * (a + 2) / 2 <= p) a++;
        int b = p - (a * cnt - a * (a + 1) / 2) + a + 1;
        float J = __logf(ns[a] + ns[b]) + g_pd[(c * CMAX + a) * CMAX + b];
        float h = fmaxf(J, 0.f);
        acc += h * h;
    }
#pragma unroll
    for (int o = 16; o; o >>= 1) acc += __shfl_xor_sync(0xffffffffu, acc, o);
    if ((tid & 31) == 0) wsum[tid >> 5] = acc;
    __syncthreads();
    if (tid == 0) {
        float s = 0.f;
#pragma unroll
        for (int w = 0; w < 8; w++) s += wsum[w];
        atomicAdd(&g_loss, s);
    }
}

// ---------------------------------------------------------------------------
// K3: finalize
// ---------------------------------------------------------------------------
__global__ void k_final(float* __restrict__ out) {
    float lp = 0.f;
    for (int c = 0; c < NCLS; c++) {
        float cc = (float)g_count[c];
        lp += cc * (cc - 1.f);
    }
    out[0] = g_loss / lp;
}

// ---------------------------------------------------------------------------
extern "C" void kernel_launch(void* const* d_in, const int* in_sizes, int n_in,
                              void* d_out, int out_size) {
    const void *Xp, *Tp;
    if (in_sizes[0] == NN * DD) { Xp = d_in[0]; Tp = d_in[1]; }
    else                        { Xp = d_in[1]; Tp = d_in[0]; }
    const float* X = (const float*)Xp;
    float* out = (float*)d_out;

    cudaFuncSetAttribute(k_gemm_mma, cudaFuncAttributeMaxDynamicSharedMemorySize,
                         SMEM_DYN);

    k_cvt<<<1, 1024>>>((const int*)Tp);
    k_rank<<<NCLS, 256>>>();
    k_sq_split<<<NN / 8, 256>>>(X);
    k_gemm_mma<<<NTRI, 256, SMEM_DYN>>>();
    k_pairs2<<<NCLS, 256>>>();
    k_final<<<1, 1>>>(out);
}

// round 14
// speedup vs baseline: 1.2818x; 1.2818x over previous
#include <cuda_runtime.h>
#include <cuda_bf16.h>
#include <cstdint>

#define NN 4096
#define DD 512
#define NCLS 64
#define CMAX 160
#define NTRI 528            // 32*33/2 upper-tri 128x128 tiles
#define GRID_GEMM 148       // persistent: 1 CTA/SM

// ---------------- device globals (scratch; no runtime alloc) ----------------
__device__ int   g_tgt[NN];
__device__ int   g_rank[NN];
__device__ int   g_members[NCLS * CMAX];
__device__ int   g_count[NCLS];
__device__ float g_sq[NN];
__device__ float g_negsum[NN];
__device__ float g_loss;
__device__ float g_pd[NCLS * CMAX * CMAX];   // dist for same-class pairs (ri<rj)
__device__ uint4 g_hi4[NN * DD / 8];         // bf16 hi split, row-major (64 uint4/row)
__device__ uint4 g_lo4[NN * DD / 8];         // bf16 lo split

// ---------------- PTX helpers ----------------
__device__ __forceinline__ uint32_t s2u(const void* p) {
    uint32_t a;
    asm("{ .reg .u64 t; cvta.to.shared.u64 t, %1; cvt.u32.u64 %0, t; }"
        : "=r"(a) : "l"(p));
    return a;
}
__device__ __forceinline__ void cp16(uint32_t saddr, const void* g) {
    asm volatile("cp.async.cg.shared.global [%0], [%1], 16;" :: "r"(saddr), "l"(g));
}
#define CP_COMMIT() asm volatile("cp.async.commit_group;" ::: "memory")
#define CP_WAIT1()  asm volatile("cp.async.wait_group 1;" ::: "memory")
#define CP_WAIT0()  asm volatile("cp.async.wait_group 0;" ::: "memory")

__device__ __forceinline__ void ldm_x4(uint32_t& r0, uint32_t& r1, uint32_t& r2,
                                       uint32_t& r3, uint32_t a) {
    asm volatile("ldmatrix.sync.aligned.m8n8.x4.shared.b16 {%0,%1,%2,%3}, [%4];"
                 : "=r"(r0), "=r"(r1), "=r"(r2), "=r"(r3) : "r"(a));
}
__device__ __forceinline__ void mma16816(float* d, const uint32_t* a, const uint32_t* b) {
    asm volatile(
        "mma.sync.aligned.m16n8k16.row.col.f32.bf16.bf16.f32 "
        "{%0,%1,%2,%3}, {%4,%5,%6,%7}, {%8,%9}, {%0,%1,%2,%3};"
        : "+f"(d[0]), "+f"(d[1]), "+f"(d[2]), "+f"(d[3])
        : "r"(a[0]), "r"(a[1]), "r"(a[2]), "r"(a[3]), "r"(b[0]), "r"(b[1]));
}
#define SW128(bo) ((bo) ^ (((bo) >> 3) & 0x70))

// ---------------- fast math (no MUFU on hot path) ----------------
__device__ __forceinline__ float fast_dist(float d2) {
    float y = __int_as_float(0x5f3759dfu - (__float_as_uint(d2) >> 1));
    y = y * fmaf(-0.5f * d2, y * y, 1.5f);
    y = y * fmaf(-0.5f * d2, y * y, 1.5f);
    return d2 > 1e-18f ? d2 * y : 0.0f;
}
__device__ __forceinline__ float exp1m(float dist) {  // exp(1 - dist)
    float t = (1.0f - dist) * 1.4426950408889634f;
    t = fmaxf(t, -125.0f);
    int n = __float2int_rn(t);
    float f = t - (float)n;
    float p = 1.3333558146e-3f;
    p = fmaf(p, f, 9.6181291076e-3f);
    p = fmaf(p, f, 5.5504108664e-2f);
    p = fmaf(p, f, 2.4022650696e-1f);
    p = fmaf(p, f, 6.9314718056e-1f);
    p = fmaf(p, f, 1.0f);
    return __int_as_float((uint32_t)(n + 127) << 23) * p;
}

// ---------------------------------------------------------------------------
// K-1: dtype-normalize targets (int32 or int64). One block, trivial.
// ---------------------------------------------------------------------------
__global__ __launch_bounds__(1024) void k_cvt(const int* __restrict__ t) {
    __shared__ int any_odd;
    int tid = threadIdx.x;
    if (tid == 0) any_odd = 0;
    __syncthreads();
    int local = 0;
    for (int i = tid; i < NN / 2; i += 1024) local |= t[2 * i + 1];
    if (local) atomicOr(&any_odd, 1);
    __syncthreads();
    bool is64 = (any_odd == 0);
    for (int i = tid; i < NN; i += 1024) g_tgt[i] = is64 ? t[2 * i] : t[i];
}

// ---------------------------------------------------------------------------
// K-0.5: per-class rank/members via block-wide ballot prefix scan.
// ---------------------------------------------------------------------------
__global__ __launch_bounds__(256) void k_rank() {
    const int c = blockIdx.x, tid = threadIdx.x;
    const int wid = tid >> 5, lane = tid & 31;
    __shared__ int wtot[8], wpre[8];
    __shared__ int base;
    if (tid == 0) base = 0;
    __syncthreads();
    for (int r0 = 0; r0 < NN; r0 += 256) {
        int i = r0 + tid;
        bool f = (g_tgt[i] == c);
        unsigned m = __ballot_sync(0xffffffffu, f);
        int myoff = __popc(m & ((1u << lane) - 1u));
        if (lane == 0) wtot[wid] = __popc(m);
        __syncthreads();
        if (tid < 8) {
            int s = 0;
            for (int w = 0; w < tid; w++) s += wtot[w];
            wpre[tid] = s;
        }
        __syncthreads();
        if (f) {
            int rk = base + wpre[wid] + myoff;
            g_rank[i] = rk;
            if (rk < CMAX) g_members[c * CMAX + rk] = i;
        }
        __syncthreads();
        if (tid == 0) {
            int s = 0;
            for (int w = 0; w < 8; w++) s += wtot[w];
            base += s;
        }
        __syncthreads();
    }
    if (tid == 0) g_count[c] = base;
}

// ---------------------------------------------------------------------------
// K0: row norms + bf16 hi/lo split + zero accumulators
// ---------------------------------------------------------------------------
__global__ __launch_bounds__(256) void k_sq_split(const float* __restrict__ X) {
    int warp = threadIdx.x >> 5, lane = threadIdx.x & 31;
    int row = blockIdx.x * 8 + warp;
    const float4* xr = (const float4*)(X + (size_t)row * DD);
    uint2* hi2 = (uint2*)g_hi4;
    uint2* lo2 = (uint2*)g_lo4;
    float s = 0.f;
#pragma unroll
    for (int q = 0; q < 4; q++) {
        int i4 = lane + q * 32;
        float4 v = xr[i4];
        s += v.x * v.x + v.y * v.y + v.z * v.z + v.w * v.w;
        union { __nv_bfloat16 b[4]; uint2 u; } H, L;
        H.b[0] = __float2bfloat16(v.x); H.b[1] = __float2bfloat16(v.y);
        H.b[2] = __float2bfloat16(v.z); H.b[3] = __float2bfloat16(v.w);
        L.b[0] = __float2bfloat16(v.x - __bfloat162float(H.b[0]));
        L.b[1] = __float2bfloat16(v.y - __bfloat162float(H.b[1]));
        L.b[2] = __float2bfloat16(v.z - __bfloat162float(H.b[2]));
        L.b[3] = __float2bfloat16(v.w - __bfloat162float(H.b[3]));
        hi2[(size_t)row * 128 + i4] = H.u;
        lo2[(size_t)row * 128 + i4] = L.u;
    }
#pragma unroll
    for (int o = 16; o; o >>= 1) s += __shfl_xor_sync(0xffffffffu, s, o);
    if (lane == 0) { g_sq[row] = s; g_negsum[row] = 0.f; }
    if (blockIdx.x == 0 && threadIdx.x == 0) g_loss = 0.f;
}

// ---------------------------------------------------------------------------
// K1: persistent split-bf16 symmetric GEMM (ldmatrix + mma.sync) with
// cross-tile cp.async pipelining. BK=64, 2-stage (128 KB), grid=148.
// ---------------------------------------------------------------------------
#define BUFSZ 16384               // one operand chunk: 128 rows x 128B
#define PHSZ  (4 * BUFSZ)         // Ahi,Alo,Bhi,Blo = 64 KB
#define NCHUNK 8                  // K=512 / 64
#define SMEM_DYN (2 * PHSZ)       // 128 KB

__device__ __forceinline__ void load_chunk(uint32_t dynb, int stage, int m0, int n0,
                                           int kq, int tid) {
#pragma unroll
    for (int op = 0; op < 4; op++) {
        const uint4* src = (op & 1) ? g_lo4 : g_hi4;
        int rb = (op < 2) ? m0 : n0;
        uint32_t dst = dynb + stage * PHSZ + op * BUFSZ;
#pragma unroll
        for (int u = 0; u < 4; u++) {
            int f = tid + u * 256;                 // 0..1023
            int r = f >> 3, c8 = f & 7;
            uint32_t bo = (uint32_t)(r * 128 + c8 * 16);
            cp16(dst + SW128(bo), &src[(size_t)(rb + r) * 64 + kq + c8]);
        }
    }
}

__device__ __forceinline__ void tile_decode(int k, int& bi, int& bj) {
    bj = (int)((sqrtf(8.f * (float)k + 1.f) - 1.f) * 0.5f);
    while ((bj + 1) * (bj + 2) / 2 <= k) bj++;
    while (bj * (bj + 1) / 2 > k) bj--;
    bi = k - bj * (bj + 1) / 2;
}

__global__ __launch_bounds__(256) void k_gemm_mma() {
    extern __shared__ __align__(1024) char dyn[];
    __shared__ int   tR[128], tC[128], rkR[128], rkC[128];
    __shared__ float sqR[128], sqC[128], rowsum[128], colsum[128];

    const int tid = threadIdx.x;
    const int lane = tid & 31;
    const int wid = tid >> 5;
    const int wm = wid & 3, wn = wid >> 2;
    const uint32_t dynb = s2u(dyn);
    const int mat = lane >> 3, rr = lane & 7;
    const int tq = lane >> 2, tr = lane & 3;

    int tix = blockIdx.x;
    if (tix >= NTRI) return;
    int bi, bj;
    tile_decode(tix, bi, bj);
    int m0 = bi * 128, n0 = bj * 128;

    // first-tile metadata + first two chunks
    for (int t = tid; t < 128; t += 256) {
        tR[t] = g_tgt[m0 + t];   tC[t] = g_tgt[n0 + t];
        sqR[t] = g_sq[m0 + t];   sqC[t] = g_sq[n0 + t];
        rkR[t] = g_rank[m0 + t]; rkC[t] = g_rank[n0 + t];
        rowsum[t] = 0.f;         colsum[t] = 0.f;
    }
    load_chunk(dynb, 0, m0, n0, 0, tid); CP_COMMIT();
    load_chunk(dynb, 1, m0, n0, 8, tid); CP_COMMIT();
    __syncthreads();

    for (;;) {
        const bool offdiag = (bi != bj);
        const int ntix = tix + GRID_GEMM;
        const bool have_next = (ntix < NTRI);
        int nbi = 0, nbj = 0, nm0 = 0, nn0 = 0;
        if (have_next) {
            tile_decode(ntix, nbi, nbj);
            nm0 = nbi * 128; nn0 = nbj * 128;
        }

        float acc[2][8][4];
#pragma unroll
        for (int mi = 0; mi < 2; mi++)
#pragma unroll
            for (int nf = 0; nf < 8; nf++)
#pragma unroll
                for (int e = 0; e < 4; e++) acc[mi][nf][e] = 0.f;

        for (int ci = 0; ci < NCHUNK; ci++) {
            if (ci == 0) { CP_WAIT1(); } else { CP_WAIT0(); }
            __syncthreads();          // chunk ci resident; prev consumers done

            if (ci >= 1 && ci < 7) {
                load_chunk(dynb, (ci + 1) & 1, m0, n0, (ci + 1) * 8, tid);
                CP_COMMIT();
            } else if (ci == 7 && have_next) {
                load_chunk(dynb, 0, nm0, nn0, 0, tid);   // next tile chunk 0
                CP_COMMIT();
            }

            const int cur = ci & 1;
            const uint32_t Ah = dynb + cur * PHSZ;
            const uint32_t Al = Ah + BUFSZ;
            const uint32_t Bh = Ah + 2 * BUFSZ;
            const uint32_t Bl = Ah + 3 * BUFSZ;

#pragma unroll
            for (int ks = 0; ks < 4; ks++) {
                uint32_t ahi[2][4], alo[2][4];
#pragma unroll
                for (int mi = 0; mi < 2; mi++) {
                    int row = wm * 32 + mi * 16 + (mat & 1) * 8 + rr;
                    uint32_t bo = (uint32_t)(row * 128 + ks * 32 + (mat >> 1) * 16);
                    uint32_t sw = SW128(bo);
                    ldm_x4(ahi[mi][0], ahi[mi][1], ahi[mi][2], ahi[mi][3], Ah + sw);
                    ldm_x4(alo[mi][0], alo[mi][1], alo[mi][2], alo[mi][3], Al + sw);
                }
                uint32_t bhi[8][2], blo[8][2];
#pragma unroll
                for (int q = 0; q < 4; q++) {
                    int row = wn * 64 + q * 16 + (mat >> 1) * 8 + rr;
                    uint32_t bo = (uint32_t)(row * 128 + ks * 32 + (mat & 1) * 16);
                    uint32_t sw = SW128(bo);
                    uint32_t r0, r1, r2, r3;
                    ldm_x4(r0, r1, r2, r3, Bh + sw);
                    bhi[2 * q][0] = r0;     bhi[2 * q][1] = r1;
                    bhi[2 * q + 1][0] = r2; bhi[2 * q + 1][1] = r3;
                    ldm_x4(r0, r1, r2, r3, Bl + sw);
                    blo[2 * q][0] = r0;     blo[2 * q][1] = r1;
                    blo[2 * q + 1][0] = r2; blo[2 * q + 1][1] = r3;
                }
#pragma unroll
                for (int mi = 0; mi < 2; mi++)
#pragma unroll
                    for (int nf = 0; nf < 8; nf++) {
                        mma16816(acc[mi][nf], ahi[mi], bhi[nf]);
                        mma16816(acc[mi][nf], ahi[mi], blo[nf]);
                        mma16816(acc[mi][nf], alo[mi], bhi[nf]);
                    }
            }
        }

        // ---- epilogue (touches only static smem; next-tile chunk0 in flight) ----
        float csum[8][2];
#pragma unroll
        for (int nf = 0; nf < 8; nf++) { csum[nf][0] = 0.f; csum[nf][1] = 0.f; }

#pragma unroll
        for (int mi = 0; mi < 2; mi++) {
#pragma unroll
            for (int h = 0; h < 2; h++) {
                int row = wm * 32 + mi * 16 + tq + h * 8;
                int ti = tR[row]; float si = sqR[row]; int ri = rkR[row];
                int gi = m0 + row;
                float rsum = 0.f;
#pragma unroll
                for (int nf = 0; nf < 8; nf++) {
#pragma unroll
                    for (int p = 0; p < 2; p++) {
                        int col = wn * 64 + nf * 8 + tr * 2 + p;
                        float dot = acc[mi][nf][h * 2 + p];
                        float d2 = fmaxf(si + sqC[col] - 2.f * dot, 0.f);
                        float dist = fast_dist(d2);
                        bool same = (ti == tC[col]);
                        float ev = same ? 0.f : exp1m(dist);
                        rsum += ev;
                        csum[nf][p] += ev;
                        if (same) {
                            int gj = n0 + col;
                            if (gi < gj) {
                                int rj = rkC[col];
                                if (ri < CMAX && rj < CMAX)
                                    g_pd[(ti * CMAX + ri) * CMAX + rj] = dist;
                            }
                        }
                    }
                }
                rsum += __shfl_xor_sync(0xffffffffu, rsum, 1);
                rsum += __shfl_xor_sync(0xffffffffu, rsum, 2);
                if (tr == 0) atomicAdd(&rowsum[row], rsum);
            }
        }
        if (offdiag) {
#pragma unroll
            for (int nf = 0; nf < 8; nf++)
#pragma unroll
                for (int p = 0; p < 2; p++) {
                    float v = csum[nf][p];
                    v += __shfl_xor_sync(0xffffffffu, v, 4);
                    v += __shfl_xor_sync(0xffffffffu, v, 8);
                    v += __shfl_xor_sync(0xffffffffu, v, 16);
                    if (lane < 4) atomicAdd(&colsum[wn * 64 + nf * 8 + lane * 2 + p], v);
                }
        }
        __syncthreads();
        for (int t = tid; t < 128; t += 256) {
            atomicAdd(&g_negsum[m0 + t], rowsum[t]);
            if (offdiag) atomicAdd(&g_negsum[n0 + t], colsum[t]);
        }
        __syncthreads();   // all reads of metadata/rowsum/iter-7 buffers complete

        if (!have_next) break;

        // next tile chunk 1 flies during metadata reload + first-chunk wait
        load_chunk(dynb, 1, nm0, nn0, 8, tid); CP_COMMIT();
        for (int t = tid; t < 128; t += 256) {
            tR[t] = g_tgt[nm0 + t];   tC[t] = g_tgt[nn0 + t];
            sqR[t] = g_sq[nm0 + t];   sqC[t] = g_sq[nn0 + t];
            rkR[t] = g_rank[nm0 + t]; rkC[t] = g_rank[nn0 + t];
            rowsum[t] = 0.f;          colsum[t] = 0.f;
        }
        __syncthreads();
        tix = ntix; bi = nbi; bj = nbj; m0 = nm0; n0 = nn0;
    }
}

// ---------------------------------------------------------------------------
// K2: positive-pair loss. Thread-per-pair flattened triangular decode.
// ---------------------------------------------------------------------------
__global__ __launch_bounds__(256) void k_pairs2() {
    __shared__ float ns[CMAX];
    __shared__ float wsum[8];
    const int c = blockIdx.x, tid = threadIdx.x;
    int cnt = g_count[c];
    if (cnt > CMAX) cnt = CMAX;
    for (int t = tid; t < cnt; t += 256)
        ns[t] = g_negsum[g_members[c * CMAX + t]];
    __syncthreads();

    const int P = cnt * (cnt - 1) / 2;
    float acc = 0.f;
    for (int p = tid; p < P; p += 256) {
        float fn = (float)cnt;
        float disc = (2.f * fn - 1.f) * (2.f * fn - 1.f) - 8.f * (float)p;
        int a = (int)((2.f * fn - 1.f - sqrtf(fmaxf(disc, 0.f))) * 0.5f);
        if (a < 0) a = 0;
        while (a > 0 && a * cnt - a * (a + 1) / 2 > p) a--;
        while ((a + 1) * cnt - (a + 1) * (a + 2) / 2 <= p) a++;
        int b = p - (a * cnt - a * (a + 1) / 2) + a + 1;
        float J = __logf(ns[a] + ns[b]) + g_pd[(c * CMAX + a) * CMAX + b];
        float h = fmaxf(J, 0.f);
        acc += h * h;
    }
#pragma unroll
    for (int o = 16; o; o >>= 1) acc += __shfl_xor_sync(0xffffffffu, acc, o);
    if ((tid & 31) == 0) wsum[tid >> 5] = acc;
    __syncthreads();
    if (tid == 0) {
        float s = 0.f;
#pragma unroll
        for (int w = 0; w < 8; w++) s += wsum[w];
        atomicAdd(&g_loss, s);
    }
}

// ---------------------------------------------------------------------------
// K3: finalize
// ---------------------------------------------------------------------------
__global__ void k_final(float* __restrict__ out) {
    float lp = 0.f;
    for (int c = 0; c < NCLS; c++) {
        float cc = (float)g_count[c];
        lp += cc * (cc - 1.f);
    }
    out[0] = g_loss / lp;
}

// ---------------------------------------------------------------------------
extern "C" void kernel_launch(void* const* d_in, const int* in_sizes, int n_in,
                              void* d_out, int out_size) {
    const void *Xp, *Tp;
    if (in_sizes[0] == NN * DD) { Xp = d_in[0]; Tp = d_in[1]; }
    else                        { Xp = d_in[1]; Tp = d_in[0]; }
    const float* X = (const float*)Xp;
    float* out = (float*)d_out;

    cudaFuncSetAttribute(k_gemm_mma, cudaFuncAttributeMaxDynamicSharedMemorySize,
                         SMEM_DYN);

    k_cvt<<<1, 1024>>>((const int*)Tp);
    k_rank<<<NCLS, 256>>>();
    k_sq_split<<<NN / 8, 256>>>(X);
    k_gemm_mma<<<GRID_GEMM, 256, SMEM_DYN>>>();
    k_pairs2<<<NCLS, 256>>>();
    k_final<<<1, 1>>>(out);
}

// round 15
// speedup vs baseline: 1.4563x; 1.1362x over previous
#include <cuda_runtime.h>
#include <cuda_bf16.h>
#include <cstdint>

#define NN 4096
#define DD 512
#define NCLS 64
#define CMAX 160
#define NTRI 528            // 32*33/2 upper-tri 128x128 tiles
#define GRID_GEMM 148       // persistent: 1 CTA/SM
#define NTHR 512            // 16 warps: 4 per SMSP

// ---------------- device globals (scratch; no runtime alloc) ----------------
__device__ int   g_tgt[NN];
__device__ int   g_rank[NN];
__device__ int   g_members[NCLS * CMAX];
__device__ int   g_count[NCLS];
__device__ float g_sq[NN];
__device__ float g_negsum[NN];
__device__ float g_loss;
__device__ float g_pd[NCLS * CMAX * CMAX];   // dist for same-class pairs (ri<rj)
__device__ uint4 g_hi4[NN * DD / 8];         // bf16 hi split, row-major (64 uint4/row)
__device__ uint4 g_lo4[NN * DD / 8];         // bf16 lo split

// ---------------- PTX helpers ----------------
__device__ __forceinline__ uint32_t s2u(const void* p) {
    uint32_t a;
    asm("{ .reg .u64 t; cvta.to.shared.u64 t, %1; cvt.u32.u64 %0, t; }"
        : "=r"(a) : "l"(p));
    return a;
}
__device__ __forceinline__ void cp16(uint32_t saddr, const void* g) {
    asm volatile("cp.async.cg.shared.global [%0], [%1], 16;" :: "r"(saddr), "l"(g));
}
#define CP_COMMIT() asm volatile("cp.async.commit_group;" ::: "memory")
#define CP_WAIT1()  asm volatile("cp.async.wait_group 1;" ::: "memory")
#define CP_WAIT0()  asm volatile("cp.async.wait_group 0;" ::: "memory")

__device__ __forceinline__ void ldm_x4(uint32_t& r0, uint32_t& r1, uint32_t& r2,
                                       uint32_t& r3, uint32_t a) {
    asm volatile("ldmatrix.sync.aligned.m8n8.x4.shared.b16 {%0,%1,%2,%3}, [%4];"
                 : "=r"(r0), "=r"(r1), "=r"(r2), "=r"(r3) : "r"(a));
}
__device__ __forceinline__ void mma16816(float* d, const uint32_t* a, const uint32_t* b) {
    asm volatile(
        "mma.sync.aligned.m16n8k16.row.col.f32.bf16.bf16.f32 "
        "{%0,%1,%2,%3}, {%4,%5,%6,%7}, {%8,%9}, {%0,%1,%2,%3};"
        : "+f"(d[0]), "+f"(d[1]), "+f"(d[2]), "+f"(d[3])
        : "r"(a[0]), "r"(a[1]), "r"(a[2]), "r"(a[3]), "r"(b[0]), "r"(b[1]));
}
#define SW128(bo) ((bo) ^ (((bo) >> 3) & 0x70))

// ---------------- fast math (no MUFU on hot path) ----------------
__device__ __forceinline__ float fast_dist(float d2) {
    float y = __int_as_float(0x5f3759dfu - (__float_as_uint(d2) >> 1));
    y = y * fmaf(-0.5f * d2, y * y, 1.5f);
    y = y * fmaf(-0.5f * d2, y * y, 1.5f);
    return d2 > 1e-18f ? d2 * y : 0.0f;
}
__device__ __forceinline__ float exp1m(float dist) {  // exp(1 - dist)
    float t = (1.0f - dist) * 1.4426950408889634f;
    t = fmaxf(t, -125.0f);
    int n = __float2int_rn(t);
    float f = t - (float)n;
    float p = 1.3333558146e-3f;
    p = fmaf(p, f, 9.6181291076e-3f);
    p = fmaf(p, f, 5.5504108664e-2f);
    p = fmaf(p, f, 2.4022650696e-1f);
    p = fmaf(p, f, 6.9314718056e-1f);
    p = fmaf(p, f, 1.0f);
    return __int_as_float((uint32_t)(n + 127) << 23) * p;
}

// ---------------------------------------------------------------------------
// K-1: dtype-normalize targets (int32 or int64). One block, trivial.
// ---------------------------------------------------------------------------
__global__ __launch_bounds__(1024) void k_cvt(const int* __restrict__ t) {
    __shared__ int any_odd;
    int tid = threadIdx.x;
    if (tid == 0) any_odd = 0;
    __syncthreads();
    int local = 0;
    for (int i = tid; i < NN / 2; i += 1024) local |= t[2 * i + 1];
    if (local) atomicOr(&any_odd, 1);
    __syncthreads();
    bool is64 = (any_odd == 0);
    for (int i = tid; i < NN; i += 1024) g_tgt[i] = is64 ? t[2 * i] : t[i];
}

// ---------------------------------------------------------------------------
// K-0.5: per-class rank/members via block-wide ballot prefix scan.
// ---------------------------------------------------------------------------
__global__ __launch_bounds__(256) void k_rank() {
    const int c = blockIdx.x, tid = threadIdx.x;
    const int wid = tid >> 5, lane = tid & 31;
    __shared__ int wtot[8], wpre[8];
    __shared__ int base;
    if (tid == 0) base = 0;
    __syncthreads();
    for (int r0 = 0; r0 < NN; r0 += 256) {
        int i = r0 + tid;
        bool f = (g_tgt[i] == c);
        unsigned m = __ballot_sync(0xffffffffu, f);
        int myoff = __popc(m & ((1u << lane) - 1u));
        if (lane == 0) wtot[wid] = __popc(m);
        __syncthreads();
        if (tid < 8) {
            int s = 0;
            for (int w = 0; w < tid; w++) s += wtot[w];
            wpre[tid] = s;
        }
        __syncthreads();
        if (f) {
            int rk = base + wpre[wid] + myoff;
            g_rank[i] = rk;
            if (rk < CMAX) g_members[c * CMAX + rk] = i;
        }
        __syncthreads();
        if (tid == 0) {
            int s = 0;
            for (int w = 0; w < 8; w++) s += wtot[w];
            base += s;
        }
        __syncthreads();
    }
    if (tid == 0) g_count[c] = base;
}

// ---------------------------------------------------------------------------
// K0: row norms + bf16 hi/lo split + zero accumulators
// ---------------------------------------------------------------------------
__global__ __launch_bounds__(256) void k_sq_split(const float* __restrict__ X) {
    int warp = threadIdx.x >> 5, lane = threadIdx.x & 31;
    int row = blockIdx.x * 8 + warp;
    const float4* xr = (const float4*)(X + (size_t)row * DD);
    uint2* hi2 = (uint2*)g_hi4;
    uint2* lo2 = (uint2*)g_lo4;
    float s = 0.f;
#pragma unroll
    for (int q = 0; q < 4; q++) {
        int i4 = lane + q * 32;
        float4 v = xr[i4];
        s += v.x * v.x + v.y * v.y + v.z * v.z + v.w * v.w;
        union { __nv_bfloat16 b[4]; uint2 u; } H, L;
        H.b[0] = __float2bfloat16(v.x); H.b[1] = __float2bfloat16(v.y);
        H.b[2] = __float2bfloat16(v.z); H.b[3] = __float2bfloat16(v.w);
        L.b[0] = __float2bfloat16(v.x - __bfloat162float(H.b[0]));
        L.b[1] = __float2bfloat16(v.y - __bfloat162float(H.b[1]));
        L.b[2] = __float2bfloat16(v.z - __bfloat162float(H.b[2]));
        L.b[3] = __float2bfloat16(v.w - __bfloat162float(H.b[3]));
        hi2[(size_t)row * 128 + i4] = H.u;
        lo2[(size_t)row * 128 + i4] = L.u;
    }
#pragma unroll
    for (int o = 16; o; o >>= 1) s += __shfl_xor_sync(0xffffffffu, s, o);
    if (lane == 0) { g_sq[row] = s; g_negsum[row] = 0.f; }
    if (blockIdx.x == 0 && threadIdx.x == 0) g_loss = 0.f;
}

// ---------------------------------------------------------------------------
// K1: persistent split-bf16 symmetric GEMM, 512 threads (16 warps, 4/SMSP),
// warp grid 4x4, each warp 32x32. BK=64 2-stage + cross-tile prefetch.
// ---------------------------------------------------------------------------
#define BUFSZ 16384               // one operand chunk: 128 rows x 128B
#define PHSZ  (4 * BUFSZ)         // Ahi,Alo,Bhi,Blo = 64 KB
#define NCHUNK 8                  // K=512 / 64
#define SMEM_DYN (2 * PHSZ)       // 128 KB

__device__ __forceinline__ void load_chunk(uint32_t dynb, int stage, int m0, int n0,
                                           int kq, int tid) {
#pragma unroll
    for (int op = 0; op < 4; op++) {
        const uint4* src = (op & 1) ? g_lo4 : g_hi4;
        int rb = (op < 2) ? m0 : n0;
        uint32_t dst = dynb + stage * PHSZ + op * BUFSZ;
#pragma unroll
        for (int u = 0; u < 2; u++) {
            int f = tid + u * NTHR;                // 0..1023
            int r = f >> 3, c8 = f & 7;
            uint32_t bo = (uint32_t)(r * 128 + c8 * 16);
            cp16(dst + SW128(bo), &src[(size_t)(rb + r) * 64 + kq + c8]);
        }
    }
}

__device__ __forceinline__ void tile_decode(int k, int& bi, int& bj) {
    bj = (int)((sqrtf(8.f * (float)k + 1.f) - 1.f) * 0.5f);
    while ((bj + 1) * (bj + 2) / 2 <= k) bj++;
    while (bj * (bj + 1) / 2 > k) bj--;
    bi = k - bj * (bj + 1) / 2;
}

__global__ __launch_bounds__(NTHR, 1) void k_gemm_mma() {
    extern __shared__ __align__(1024) char dyn[];
    __shared__ int   tR[128], tC[128], rkR[128], rkC[128];
    __shared__ float sqR[128], sqC[128], rowsum[128], colsum[128];

    const int tid = threadIdx.x;
    const int lane = tid & 31;
    const int wid = tid >> 5;
    const int wm = wid & 3, wn = wid >> 2;     // 4x4 warp grid, 32x32 each
    const uint32_t dynb = s2u(dyn);
    const int mat = lane >> 3, rr = lane & 7;
    const int tq = lane >> 2, tr = lane & 3;

    int tix = blockIdx.x;
    if (tix >= NTRI) return;
    int bi, bj;
    tile_decode(tix, bi, bj);
    int m0 = bi * 128, n0 = bj * 128;

    if (tid < 128) {
        int t = tid;
        tR[t] = g_tgt[m0 + t];   tC[t] = g_tgt[n0 + t];
        sqR[t] = g_sq[m0 + t];   sqC[t] = g_sq[n0 + t];
        rkR[t] = g_rank[m0 + t]; rkC[t] = g_rank[n0 + t];
        rowsum[t] = 0.f;         colsum[t] = 0.f;
    }
    load_chunk(dynb, 0, m0, n0, 0, tid); CP_COMMIT();
    load_chunk(dynb, 1, m0, n0, 8, tid); CP_COMMIT();
    __syncthreads();

    for (;;) {
        const bool offdiag = (bi != bj);
        const int ntix = tix + GRID_GEMM;
        const bool have_next = (ntix < NTRI);
        int nbi = 0, nbj = 0, nm0 = 0, nn0 = 0;
        if (have_next) {
            tile_decode(ntix, nbi, nbj);
            nm0 = nbi * 128; nn0 = nbj * 128;
        }

        float acc[2][4][4];
#pragma unroll
        for (int mi = 0; mi < 2; mi++)
#pragma unroll
            for (int nf = 0; nf < 4; nf++)
#pragma unroll
                for (int e = 0; e < 4; e++) acc[mi][nf][e] = 0.f;

        for (int ci = 0; ci < NCHUNK; ci++) {
            if (ci == 0) { CP_WAIT1(); } else { CP_WAIT0(); }
            __syncthreads();          // chunk ci resident; prev consumers done

            if (ci >= 1 && ci < 7) {
                load_chunk(dynb, (ci + 1) & 1, m0, n0, (ci + 1) * 8, tid);
                CP_COMMIT();
            } else if (ci == 7 && have_next) {
                load_chunk(dynb, 0, nm0, nn0, 0, tid);   // next tile chunk 0
                CP_COMMIT();
            }

            const int cur = ci & 1;
            const uint32_t Ah = dynb + cur * PHSZ;
            const uint32_t Al = Ah + BUFSZ;
            const uint32_t Bh = Ah + 2 * BUFSZ;
            const uint32_t Bl = Ah + 3 * BUFSZ;

#pragma unroll
            for (int ks = 0; ks < 4; ks++) {
                uint32_t ahi[2][4], alo[2][4];
#pragma unroll
                for (int mi = 0; mi < 2; mi++) {
                    int row = wm * 32 + mi * 16 + (mat & 1) * 8 + rr;
                    uint32_t bo = (uint32_t)(row * 128 + ks * 32 + (mat >> 1) * 16);
                    uint32_t sw = SW128(bo);
                    ldm_x4(ahi[mi][0], ahi[mi][1], ahi[mi][2], ahi[mi][3], Ah + sw);
                    ldm_x4(alo[mi][0], alo[mi][1], alo[mi][2], alo[mi][3], Al + sw);
                }
                uint32_t bhi[4][2], blo[4][2];
#pragma unroll
                for (int q = 0; q < 2; q++) {
                    int row = wn * 32 + q * 16 + (mat >> 1) * 8 + rr;
                    uint32_t bo = (uint32_t)(row * 128 + ks * 32 + (mat & 1) * 16);
                    uint32_t sw = SW128(bo);
                    uint32_t r0, r1, r2, r3;
                    ldm_x4(r0, r1, r2, r3, Bh + sw);
                    bhi[2 * q][0] = r0;     bhi[2 * q][1] = r1;
                    bhi[2 * q + 1][0] = r2; bhi[2 * q + 1][1] = r3;
                    ldm_x4(r0, r1, r2, r3, Bl + sw);
                    blo[2 * q][0] = r0;     blo[2 * q][1] = r1;
                    blo[2 * q + 1][0] = r2; blo[2 * q + 1][1] = r3;
                }
#pragma unroll
                for (int mi = 0; mi < 2; mi++)
#pragma unroll
                    for (int nf = 0; nf < 4; nf++) {
                        mma16816(acc[mi][nf], ahi[mi], bhi[nf]);
                        mma16816(acc[mi][nf], ahi[mi], blo[nf]);
                        mma16816(acc[mi][nf], alo[mi], bhi[nf]);
                    }
            }
        }

        // ---- epilogue (static smem only; next-tile chunk0 in flight) ----
        float csum[4][2];
#pragma unroll
        for (int nf = 0; nf < 4; nf++) { csum[nf][0] = 0.f; csum[nf][1] = 0.f; }

#pragma unroll
        for (int mi = 0; mi < 2; mi++) {
#pragma unroll
            for (int h = 0; h < 2; h++) {
                int row = wm * 32 + mi * 16 + tq + h * 8;
                int ti = tR[row]; float si = sqR[row]; int ri = rkR[row];
                int gi = m0 + row;
                float rsum = 0.f;
#pragma unroll
                for (int nf = 0; nf < 4; nf++) {
#pragma unroll
                    for (int p = 0; p < 2; p++) {
                        int col = wn * 32 + nf * 8 + tr * 2 + p;
                        float dot = acc[mi][nf][h * 2 + p];
                        float d2 = fmaxf(si + sqC[col] - 2.f * dot, 0.f);
                        float dist = fast_dist(d2);
                        bool same = (ti == tC[col]);
                        float ev = same ? 0.f : exp1m(dist);
                        rsum += ev;
                        csum[nf][p] += ev;
                        if (same) {
                            int gj = n0 + col;
                            if (gi < gj) {
                                int rj = rkC[col];
                                if (ri < CMAX && rj < CMAX)
                                    g_pd[(ti * CMAX + ri) * CMAX + rj] = dist;
                            }
                        }
                    }
                }
                rsum += __shfl_xor_sync(0xffffffffu, rsum, 1);
                rsum += __shfl_xor_sync(0xffffffffu, rsum, 2);
                if (tr == 0) atomicAdd(&rowsum[row], rsum);
            }
        }
        if (offdiag) {
#pragma unroll
            for (int nf = 0; nf < 4; nf++)
#pragma unroll
                for (int p = 0; p < 2; p++) {
                    float v = csum[nf][p];
                    v += __shfl_xor_sync(0xffffffffu, v, 4);
                    v += __shfl_xor_sync(0xffffffffu, v, 8);
                    v += __shfl_xor_sync(0xffffffffu, v, 16);
                    if (lane < 4) atomicAdd(&colsum[wn * 32 + nf * 8 + lane * 2 + p], v);
                }
        }
        __syncthreads();
        if (tid < 128) {
            atomicAdd(&g_negsum[m0 + tid], rowsum[tid]);
            if (offdiag) atomicAdd(&g_negsum[n0 + tid], colsum[tid]);
        }
        __syncthreads();   // reads of metadata/rowsum/iter-7 buffers complete

        if (!have_next) break;

        load_chunk(dynb, 1, nm0, nn0, 8, tid); CP_COMMIT();
        if (tid < 128) {
            int t = tid;
            tR[t] = g_tgt[nm0 + t];   tC[t] = g_tgt[nn0 + t];
            sqR[t] = g_sq[nm0 + t];   sqC[t] = g_sq[nn0 + t];
            rkR[t] = g_rank[nm0 + t]; rkC[t] = g_rank[nn0 + t];
            rowsum[t] = 0.f;          colsum[t] = 0.f;
        }
        __syncthreads();
        tix = ntix; bi = nbi; bj = nbj; m0 = nm0; n0 = nn0;
    }
}

// ---------------------------------------------------------------------------
// K2: positive-pair loss. Thread-per-pair flattened triangular decode.
// ---------------------------------------------------------------------------
__global__ __launch_bounds__(256) void k_pairs2() {
    __shared__ float ns[CMAX];
    __shared__ float wsum[8];
    const int c = blockIdx.x, tid = threadIdx.x;
    int cnt = g_count[c];
    if (cnt > CMAX) cnt = CMAX;
    for (int t = tid; t < cnt; t += 256)
        ns[t] = g_negsum[g_members[c * CMAX + t]];
    __syncthreads();

    const int P = cnt * (cnt - 1) / 2;
    float acc = 0.f;
    for (int p = tid; p < P; p += 256) {
        float fn = (float)cnt;
        float disc = (2.f * fn - 1.f) * (2.f * fn - 1.f) - 8.f * (float)p;
        int a = (int)((2.f * fn - 1.f - sqrtf(fmaxf(disc, 0.f))) * 0.5f);
        if (a < 0) a = 0;
        while (a > 0 && a * cnt - a * (a + 1) / 2 > p) a--;
        while ((a + 1) * cnt - (a + 1) * (a + 2) / 2 <= p) a++;
        int b = p - (a * cnt - a * (a + 1) / 2) + a + 1;
        float J = __logf(ns[a] + ns[b]) + g_pd[(c * CMAX + a) * CMAX + b];
        float h = fmaxf(J, 0.f);
        acc += h * h;
    }
#pragma unroll
    for (int o = 16; o; o >>= 1) acc += __shfl_xor_sync(0xffffffffu, acc, o);
    if ((tid & 31) == 0) wsum[tid >> 5] = acc;
    __syncthreads();
    if (tid == 0) {
        float s = 0.f;
#pragma unroll
        for (int w = 0; w < 8; w++) s += wsum[w];
        atomicAdd(&g_loss, s);
    }
}

// ---------------------------------------------------------------------------
// K3: finalize
// ---------------------------------------------------------------------------
__global__ void k_final(float* __restrict__ out) {
    float lp = 0.f;
    for (int c = 0; c < NCLS; c++) {
        float cc = (float)g_count[c];
        lp += cc * (cc - 1.f);
    }
    out[0] = g_loss / lp;
}

// ---------------------------------------------------------------------------
extern "C" void kernel_launch(void* const* d_in, const int* in_sizes, int n_in,
                              void* d_out, int out_size) {
    const void *Xp, *Tp;
    if (in_sizes[0] == NN * DD) { Xp = d_in[0]; Tp = d_in[1]; }
    else                        { Xp = d_in[1]; Tp = d_in[0]; }
    const float* X = (const float*)Xp;
    float* out = (float*)d_out;

    cudaFuncSetAttribute(k_gemm_mma, cudaFuncAttributeMaxDynamicSharedMemorySize,
                         SMEM_DYN);

    k_cvt<<<1, 1024>>>((const int*)Tp);
    k_rank<<<NCLS, 256>>>();
    k_sq_split<<<NN / 8, 256>>>(X);
    k_gemm_mma<<<GRID_GEMM, NTHR, SMEM_DYN>>>();
    k_pairs2<<<NCLS, 256>>>();
    k_final<<<1, 1>>>(out);
}